// round 15
// baseline (speedup 1.0000x reference)
#include <cuda_runtime.h>

#define NB 4
#define NV 4096
#define NT 8192
#define NP 4096
#define EPSF 1e-12f
#define BIGF 3.402823466e38f

#define TPB 128
#define PPT 4              // points per thread (2 packed f32x2 streams)
#define CHUNKS_X 114       // 114*8*4 = 3648 blocks = 4 x 912 (6 blocks/SM x 152 SMs)
#define MAX_CNT 72         // ceil(8192/114)
#define F4_PER_TRI 9       // 144 bytes per triangle, constants pre-duplicated

typedef unsigned long long ull;

static __device__ float4 g_tri2[NB * NT * F4_PER_TRI];
static __device__ unsigned int g_dmin[NB * NP];
static __device__ float g_psum[64];
static __device__ float g_pcnt[64];

// ---------- packed f32x2 helpers (SASS FADD2/FMUL2/FFMA2) ----------
__device__ __forceinline__ ull f2x(float lo, float hi) {
    ull r; asm("mov.b64 %0, {%1, %2};" : "=l"(r) : "f"(lo), "f"(hi)); return r;
}
__device__ __forceinline__ ull f2x_add(ull a, ull b) {
    ull r; asm("add.rn.f32x2 %0, %1, %2;" : "=l"(r) : "l"(a), "l"(b)); return r;
}
__device__ __forceinline__ ull f2x_mul(ull a, ull b) {
    ull r; asm("mul.rn.f32x2 %0, %1, %2;" : "=l"(r) : "l"(a), "l"(b)); return r;
}
__device__ __forceinline__ ull f2x_fma(ull a, ull b, ull c) {
    ull r; asm("fma.rn.f32x2 %0, %1, %2, %3;" : "=l"(r) : "l"(a), "l"(b), "l"(c)); return r;
}
__device__ __forceinline__ float f2lo(ull v) { return __uint_as_float((unsigned)v); }
__device__ __forceinline__ float f2hi(ull v) { return __uint_as_float((unsigned)(v >> 32)); }

__device__ __forceinline__ float safe_inv(float x) {
    return (fabsf(x) < EPSF) ? 1.0f : (1.0f / x);
}
__device__ __forceinline__ float sigm(float v) {
    return 1.0f / (1.0f + expf(-v));
}

// Kernel 1: per-triangle precompute (sigmoid fused in — no separate prep pass),
// plus dmin init. Constants duplicated into f32x2 pairs.
// Pair map: c0:(-ax,-ay) c1:(-az,abx) c2:(aby,abz) c3:(acx,acy) c4:(acz,-ab2)
//           c5:(-abac,-ac2) c6:(-iab2,-iac2) c7:(-ibc2,den) c8:(-iden,0)
__global__ void tri_kernel(const float* __restrict__ vertices,
                           const int* __restrict__ faces) {
    int idx = blockIdx.x * blockDim.x + threadIdx.x;
    if (idx < NB * NP) g_dmin[idx] = 0x7F7FFFFFu;  // +FLT_MAX bits
    if (idx >= NB * NT) return;
    int b = idx >> 13;
    int t = idx & (NT - 1);
    int i0 = faces[t * 3 + 0], i1 = faces[t * 3 + 1], i2 = faces[t * 3 + 2];
    const float* base = vertices + (size_t)b * 3 * NV;   // layout (3, NV) per batch
    float ax = sigm(base[i0]),          ay = sigm(base[NV + i0]),  az = sigm(base[2 * NV + i0]);
    float bx = sigm(base[i1]),          by = sigm(base[NV + i1]),  bz = sigm(base[2 * NV + i1]);
    float cx = sigm(base[i2]),          cy = sigm(base[NV + i2]),  cz = sigm(base[2 * NV + i2]);
    float abx = bx - ax, aby = by - ay, abz = bz - az;
    float acx = cx - ax, acy = cy - ay, acz = cz - az;
    float bcx = cx - bx, bcy = cy - by, bcz = cz - bz;
    float ab2  = abx * abx + aby * aby + abz * abz;
    float ac2  = acx * acx + acy * acy + acz * acz;
    float abac = abx * acx + aby * acy + abz * acz;
    float bc2  = bcx * bcx + bcy * bcy + bcz * bcz;
    float den  = ab2 * ac2 - abac * abac;   // == va+vb+vc
    float4* o = g_tri2 + (size_t)idx * F4_PER_TRI;
    o[0] = make_float4(-ax, -ax, -ay, -ay);
    o[1] = make_float4(-az, -az, abx, abx);
    o[2] = make_float4(aby, aby, abz, abz);
    o[3] = make_float4(acx, acx, acy, acy);
    o[4] = make_float4(acz, acz, -ab2, -ab2);
    o[5] = make_float4(-abac, -abac, -ac2, -ac2);
    o[6] = make_float4(-safe_inv(ab2), -safe_inv(ab2), -safe_inv(ac2), -safe_inv(ac2));
    o[7] = make_float4(-safe_inv(bc2), -safe_inv(bc2), den, den);
    o[8] = make_float4(-safe_inv(den), -safe_inv(den), 0.0f, 0.0f);
}

// Min-of-features closest distance, one triangle vs two packed points.
// m = min(pa2, pb2, pc2,
//         lineAB if 0<d1<ab2, lineAC if 0<d2<ac2 (d6<0), lineBC if e>0 && f>0,
//         face   if va,vb,vc > 0)
__device__ __forceinline__ void tri_pair(const ulonglong2* __restrict__ tp,
                                         ull px, ull py, ull pz, ull NEG1,
                                         float& m0, float& m1)
{
    ulonglong2 c0 = tp[0], c1 = tp[1], c2 = tp[2], c3 = tp[3], c4 = tp[4];
    ull apx = f2x_add(px, c0.x);
    ull apy = f2x_add(py, c0.y);
    ull apz = f2x_add(pz, c1.x);
    ull pa2 = f2x_fma(apx, apx, f2x_fma(apy, apy, f2x_mul(apz, apz)));
    ull d1  = f2x_fma(c1.y, apx, f2x_fma(c2.x, apy, f2x_mul(c2.y, apz)));
    ull d2  = f2x_fma(c3.x, apx, f2x_fma(c3.y, apy, f2x_mul(c4.x, apz)));
    ulonglong2 c5 = tp[5], c6 = tp[6], c7 = tp[7], c8 = tp[8];
    ull d3 = f2x_add(d1, c4.y);            // d1 - ab2
    ull d4 = f2x_add(d2, c5.x);            // d2 - abac
    ull d5 = f2x_add(d1, c5.x);            // d1 - abac
    ull d6 = f2x_add(d2, c5.y);            // d2 - ac2
    ull pb2 = f2x_fma(f2x_add(d1, d3), NEG1, pa2);
    ull pc2 = f2x_fma(f2x_add(d2, d6), NEG1, pa2);
    ull e = f2x_fma(d3, NEG1, d4);
    ull f = f2x_fma(d6, NEG1, d5);
    ull vAB = f2x_fma(f2x_mul(d1, d1), c6.x, pa2);
    ull vAC = f2x_fma(f2x_mul(d2, d2), c6.y, pa2);
    ull vBC = f2x_fma(f2x_mul(e, e), c7.x, pb2);
    ull vb = f2x_fma(f2x_mul(d1, d6), NEG1, f2x_mul(d5, d2));
    ull vc = f2x_fma(f2x_mul(d3, d2), NEG1, f2x_mul(d1, d4));
    ull va = f2x_fma(f2x_add(vb, vc), NEG1, c7.y);
    ull dI = f2x_fma(f2x_fma(vc, d2, f2x_mul(vb, d1)), c8.x, pa2);

    // lane 0
    {
        float m = fminf(f2lo(pa2), fminf(f2lo(pb2), f2lo(pc2)));
        if (f2lo(d1) > 0.0f && f2lo(d3) < 0.0f) m = fminf(m, f2lo(vAB));
        if (f2lo(d2) > 0.0f && f2lo(d6) < 0.0f) m = fminf(m, f2lo(vAC));
        if (f2lo(e) > 0.0f && f2lo(f) > 0.0f) m = fminf(m, f2lo(vBC));
        if (fminf(f2lo(va), fminf(f2lo(vb), f2lo(vc))) > 0.0f) m = fminf(m, f2lo(dI));
        m0 = fminf(m0, m);
    }
    // lane 1
    {
        float m = fminf(f2hi(pa2), fminf(f2hi(pb2), f2hi(pc2)));
        if (f2hi(d1) > 0.0f && f2hi(d3) < 0.0f) m = fminf(m, f2hi(vAB));
        if (f2hi(d2) > 0.0f && f2hi(d6) < 0.0f) m = fminf(m, f2hi(vAC));
        if (f2hi(e) > 0.0f && f2hi(f) > 0.0f) m = fminf(m, f2hi(vBC));
        if (fminf(f2hi(va), fminf(f2hi(vb), f2hi(vc))) > 0.0f) m = fminf(m, f2hi(dI));
        m1 = fminf(m1, m);
    }
}

// Kernel 2: brute-force min over triangles, packed f32x2, smem-staged tris.
// Grid 114x8x4 = 3648 blocks (71-72 tris each). launch_bounds(128,6) caps regs
// at 85 -> 6 blocks/SM -> 912 resident on 152 SMs -> exactly 4 full waves AND
// +20% warps/SMSP vs the 5-block config (occupancy re-test with tail removed).
__global__ void __launch_bounds__(TPB, 6) dist_kernel(const float* __restrict__ pc) {
    __shared__ float4 sT[MAX_CNT * F4_PER_TRI];
    int b = blockIdx.z;
    int tid = threadIdx.x;
    const float* P = pc + (size_t)b * NP * 3;
    int ibase = blockIdx.y * (PPT * TPB) + tid;

    float px[PPT], py[PPT], pz[PPT];
#pragma unroll
    for (int k = 0; k < PPT; k++) {
        int i = ibase + k * TPB;
        px[k] = P[i * 3 + 0];
        py[k] = P[i * 3 + 1];
        pz[k] = P[i * 3 + 2];
    }
    ull px2[2], py2[2], pz2[2];
#pragma unroll
    for (int j = 0; j < 2; j++) {
        px2[j] = f2x(px[2 * j], px[2 * j + 1]);
        py2[j] = f2x(py[2 * j], py[2 * j + 1]);
        pz2[j] = f2x(pz[2 * j], pz[2 * j + 1]);
    }
    const ull NEG1 = f2x(-1.0f, -1.0f);
    float dm[PPT];
#pragma unroll
    for (int k = 0; k < PPT; k++) dm[k] = BIGF;

    int x = blockIdx.x;
    int tstart = (x * NT) / CHUNKS_X;
    int tend = ((x + 1) * NT) / CHUNKS_X;
    int cnt = tend - tstart;               // 71 or 72

    const float4* src = g_tri2 + ((size_t)b * NT + tstart) * F4_PER_TRI;
    for (int i = tid; i < cnt * F4_PER_TRI; i += TPB)
        sT[i] = src[i];
    __syncthreads();
#pragma unroll 2
    for (int t = 0; t < cnt; t++) {
        const ulonglong2* tp = reinterpret_cast<const ulonglong2*>(sT + t * F4_PER_TRI);
        tri_pair(tp, px2[0], py2[0], pz2[0], NEG1, dm[0], dm[1]);
        tri_pair(tp, px2[1], py2[1], pz2[1], NEG1, dm[2], dm[3]);
    }
#pragma unroll
    for (int k = 0; k < PPT; k++)
        atomicMin(&g_dmin[b * NP + ibase + k * TPB], __float_as_uint(dm[k]));
}

// Kernel 3a: parallel partial reduce. 64 blocks (16 slices x 4 batches) x 256 thr.
__global__ void reduceA_kernel(const float* __restrict__ pc) {
    __shared__ float sd[256];
    __shared__ float sc[256];
    int tid = threadIdx.x;
    int blk = blockIdx.x;
    int b = blk >> 4;
    int slice = blk & 15;
    int i = slice * 256 + tid;
    const float* p = pc + ((size_t)b * NP + i) * 3;
    float x = p[0], y = p[1], z = p[2];
    float m = (x != 0.0f || y != 0.0f || z != 0.0f) ? 1.0f : 0.0f;
    sd[tid] = __uint_as_float(g_dmin[b * NP + i]) * m;
    sc[tid] = m;
    __syncthreads();
    for (int s = 128; s > 0; s >>= 1) {
        if (tid < s) {
            sd[tid] += sd[tid + s];
            sc[tid] += sc[tid + s];
        }
        __syncthreads();
    }
    if (tid == 0) {
        g_psum[blk] = sd[0];
        g_pcnt[blk] = sc[0];
    }
}

// Kernel 3b: deterministic fixed-order final combine.
__global__ void reduceB_kernel(float* __restrict__ out) {
    if (threadIdx.x == 0) {
        float acc = 0.0f;
        for (int b = 0; b < NB; b++) {
            float s = 0.0f, c = 0.0f;
#pragma unroll
            for (int j = 0; j < 16; j++) {
                s += g_psum[b * 16 + j];
                c += g_pcnt[b * 16 + j];
            }
            acc += s / fmaxf(c, 1.0f);
        }
        out[0] = acc * (1.0f / NB);
    }
}

extern "C" void kernel_launch(void* const* d_in, const int* in_sizes, int n_in,
                              void* d_out, int out_size) {
    const float* vertices = (const float*)d_in[0];
    const float* pc = (const float*)d_in[1];
    const int* faces = (const int*)d_in[2];
    float* out = (float*)d_out;

    tri_kernel<<<(NB * NT + 255) / 256, 256>>>(vertices, faces);
    dist_kernel<<<dim3(CHUNKS_X, NP / (PPT * TPB), NB), TPB>>>(pc);
    reduceA_kernel<<<64, 256>>>(pc);
    reduceB_kernel<<<1, 32>>>(out);
}

// round 16
// speedup vs baseline: 1.0782x; 1.0782x over previous
#include <cuda_runtime.h>

#define NB 4
#define NV 4096
#define NT 8192
#define NP 4096
#define EPSF 1e-12f
#define BIGF 3.402823466e38f

#define TPB 128
#define PPT 4              // points per thread (2 packed f32x2 streams)
#define CHUNKS_X 95        // 95*8*4 = 3040 blocks = 4x760 = 5x608 (exact waves)
#define MAX_CNT 87         // ceil(8192/95)
#define F4_PER_TRI 9       // 144 bytes per triangle, constants pre-duplicated

typedef unsigned long long ull;

static __device__ float4 g_tri2[NB * NT * F4_PER_TRI];
static __device__ unsigned int g_dmin[NB * NP];
static __device__ float g_psum[64];
static __device__ float g_pcnt[64];

// ---------- packed f32x2 helpers (SASS FADD2/FMUL2/FFMA2) ----------
__device__ __forceinline__ ull f2x(float lo, float hi) {
    ull r; asm("mov.b64 %0, {%1, %2};" : "=l"(r) : "f"(lo), "f"(hi)); return r;
}
__device__ __forceinline__ ull f2x_add(ull a, ull b) {
    ull r; asm("add.rn.f32x2 %0, %1, %2;" : "=l"(r) : "l"(a), "l"(b)); return r;
}
__device__ __forceinline__ ull f2x_mul(ull a, ull b) {
    ull r; asm("mul.rn.f32x2 %0, %1, %2;" : "=l"(r) : "l"(a), "l"(b)); return r;
}
__device__ __forceinline__ ull f2x_fma(ull a, ull b, ull c) {
    ull r; asm("fma.rn.f32x2 %0, %1, %2, %3;" : "=l"(r) : "l"(a), "l"(b), "l"(c)); return r;
}
__device__ __forceinline__ float f2lo(ull v) { return __uint_as_float((unsigned)v); }
__device__ __forceinline__ float f2hi(ull v) { return __uint_as_float((unsigned)(v >> 32)); }

__device__ __forceinline__ float safe_inv(float x) {
    return (fabsf(x) < EPSF) ? 1.0f : (1.0f / x);
}
__device__ __forceinline__ float sigm(float v) {
    return 1.0f / (1.0f + expf(-v));
}

// Kernel 1: per-triangle precompute (sigmoid fused — no separate prep pass),
// plus dmin init. Constants duplicated into f32x2 pairs.
// Pair map: c0:(-ax,-ay) c1:(-az,abx) c2:(aby,abz) c3:(acx,acy) c4:(acz,-ab2)
//           c5:(-abac,-ac2) c6:(-iab2,-iac2) c7:(-ibc2,den) c8:(-iden,0)
__global__ void tri_kernel(const float* __restrict__ vertices,
                           const int* __restrict__ faces) {
    int idx = blockIdx.x * blockDim.x + threadIdx.x;
    if (idx < NB * NP) g_dmin[idx] = 0x7F7FFFFFu;  // +FLT_MAX bits
    if (idx >= NB * NT) return;
    int b = idx >> 13;
    int t = idx & (NT - 1);
    int i0 = faces[t * 3 + 0], i1 = faces[t * 3 + 1], i2 = faces[t * 3 + 2];
    const float* base = vertices + (size_t)b * 3 * NV;   // layout (3, NV) per batch
    float ax = sigm(base[i0]), ay = sigm(base[NV + i0]), az = sigm(base[2 * NV + i0]);
    float bx = sigm(base[i1]), by = sigm(base[NV + i1]), bz = sigm(base[2 * NV + i1]);
    float cx = sigm(base[i2]), cy = sigm(base[NV + i2]), cz = sigm(base[2 * NV + i2]);
    float abx = bx - ax, aby = by - ay, abz = bz - az;
    float acx = cx - ax, acy = cy - ay, acz = cz - az;
    float bcx = cx - bx, bcy = cy - by, bcz = cz - bz;
    float ab2  = abx * abx + aby * aby + abz * abz;
    float ac2  = acx * acx + acy * acy + acz * acz;
    float abac = abx * acx + aby * acy + abz * acz;
    float bc2  = bcx * bcx + bcy * bcy + bcz * bcz;
    float den  = ab2 * ac2 - abac * abac;   // == va+vb+vc
    float4* o = g_tri2 + (size_t)idx * F4_PER_TRI;
    o[0] = make_float4(-ax, -ax, -ay, -ay);
    o[1] = make_float4(-az, -az, abx, abx);
    o[2] = make_float4(aby, aby, abz, abz);
    o[3] = make_float4(acx, acx, acy, acy);
    o[4] = make_float4(acz, acz, -ab2, -ab2);
    o[5] = make_float4(-abac, -abac, -ac2, -ac2);
    o[6] = make_float4(-safe_inv(ab2), -safe_inv(ab2), -safe_inv(ac2), -safe_inv(ac2));
    o[7] = make_float4(-safe_inv(bc2), -safe_inv(bc2), den, den);
    o[8] = make_float4(-safe_inv(den), -safe_inv(den), 0.0f, 0.0f);
}

// Min-of-features closest distance, one triangle vs two packed points.
// m = min(pa2, pb2, pc2,
//         lineAB if 0<d1<ab2, lineAC if 0<d2<ac2 (d6<0), lineBC if e>0 && f>0,
//         face   if va,vb,vc > 0)
__device__ __forceinline__ void tri_pair(const ulonglong2* __restrict__ tp,
                                         ull px, ull py, ull pz, ull NEG1,
                                         float& m0, float& m1)
{
    ulonglong2 c0 = tp[0], c1 = tp[1], c2 = tp[2], c3 = tp[3], c4 = tp[4];
    ull apx = f2x_add(px, c0.x);
    ull apy = f2x_add(py, c0.y);
    ull apz = f2x_add(pz, c1.x);
    ull pa2 = f2x_fma(apx, apx, f2x_fma(apy, apy, f2x_mul(apz, apz)));
    ull d1  = f2x_fma(c1.y, apx, f2x_fma(c2.x, apy, f2x_mul(c2.y, apz)));
    ull d2  = f2x_fma(c3.x, apx, f2x_fma(c3.y, apy, f2x_mul(c4.x, apz)));
    ulonglong2 c5 = tp[5], c6 = tp[6], c7 = tp[7], c8 = tp[8];
    ull d3 = f2x_add(d1, c4.y);            // d1 - ab2
    ull d4 = f2x_add(d2, c5.x);            // d2 - abac
    ull d5 = f2x_add(d1, c5.x);            // d1 - abac
    ull d6 = f2x_add(d2, c5.y);            // d2 - ac2
    ull pb2 = f2x_fma(f2x_add(d1, d3), NEG1, pa2);
    ull pc2 = f2x_fma(f2x_add(d2, d6), NEG1, pa2);
    ull e = f2x_fma(d3, NEG1, d4);
    ull f = f2x_fma(d6, NEG1, d5);
    ull vAB = f2x_fma(f2x_mul(d1, d1), c6.x, pa2);
    ull vAC = f2x_fma(f2x_mul(d2, d2), c6.y, pa2);
    ull vBC = f2x_fma(f2x_mul(e, e), c7.x, pb2);
    ull vb = f2x_fma(f2x_mul(d1, d6), NEG1, f2x_mul(d5, d2));
    ull vc = f2x_fma(f2x_mul(d3, d2), NEG1, f2x_mul(d1, d4));
    ull va = f2x_fma(f2x_add(vb, vc), NEG1, c7.y);
    ull dI = f2x_fma(f2x_fma(vc, d2, f2x_mul(vb, d1)), c8.x, pa2);

    // lane 0
    {
        float m = fminf(f2lo(pa2), fminf(f2lo(pb2), f2lo(pc2)));
        if (f2lo(d1) > 0.0f && f2lo(d3) < 0.0f) m = fminf(m, f2lo(vAB));
        if (f2lo(d2) > 0.0f && f2lo(d6) < 0.0f) m = fminf(m, f2lo(vAC));
        if (f2lo(e) > 0.0f && f2lo(f) > 0.0f) m = fminf(m, f2lo(vBC));
        if (fminf(f2lo(va), fminf(f2lo(vb), f2lo(vc))) > 0.0f) m = fminf(m, f2lo(dI));
        m0 = fminf(m0, m);
    }
    // lane 1
    {
        float m = fminf(f2hi(pa2), fminf(f2hi(pb2), f2hi(pc2)));
        if (f2hi(d1) > 0.0f && f2hi(d3) < 0.0f) m = fminf(m, f2hi(vAB));
        if (f2hi(d2) > 0.0f && f2hi(d6) < 0.0f) m = fminf(m, f2hi(vAC));
        if (f2hi(e) > 0.0f && f2hi(f) > 0.0f) m = fminf(m, f2hi(vBC));
        if (fminf(f2hi(va), fminf(f2hi(vb), f2hi(vc))) > 0.0f) m = fminf(m, f2hi(dI));
        m1 = fminf(m1, m);
    }
}

// Kernel 2: brute-force min over triangles, packed f32x2, smem-staged tris.
// R14-winning config: grid 95x8x4 = 3040 blocks (86-87 tris each), smem padded
// to ~39KB to pin residency at 5 blocks/SM (760 resident on 152 SMs -> 4 exact
// waves; if regs force 4/SM -> 608 -> 5 exact waves). NO max-blocks clamp —
// R15 proved launch_bounds(,6) forces hot-loop spills (+18us).
__global__ void __launch_bounds__(TPB) dist_kernel(const float* __restrict__ pc) {
    __shared__ float4 sT[MAX_CNT * F4_PER_TRI];
    __shared__ char s_pad[26496];          // occupancy pin: total smem > 228KB/6
    int b = blockIdx.z;
    int tid = threadIdx.x;
    if (tid > 100000) ((volatile char*)s_pad)[0] = 1;   // keep pad allocated
    const float* P = pc + (size_t)b * NP * 3;
    int ibase = blockIdx.y * (PPT * TPB) + tid;

    float px[PPT], py[PPT], pz[PPT];
#pragma unroll
    for (int k = 0; k < PPT; k++) {
        int i = ibase + k * TPB;
        px[k] = P[i * 3 + 0];
        py[k] = P[i * 3 + 1];
        pz[k] = P[i * 3 + 2];
    }
    ull px2[2], py2[2], pz2[2];
#pragma unroll
    for (int j = 0; j < 2; j++) {
        px2[j] = f2x(px[2 * j], px[2 * j + 1]);
        py2[j] = f2x(py[2 * j], py[2 * j + 1]);
        pz2[j] = f2x(pz[2 * j], pz[2 * j + 1]);
    }
    const ull NEG1 = f2x(-1.0f, -1.0f);
    float dm[PPT];
#pragma unroll
    for (int k = 0; k < PPT; k++) dm[k] = BIGF;

    int x = blockIdx.x;
    int tstart = (x * NT) / CHUNKS_X;
    int tend = ((x + 1) * NT) / CHUNKS_X;
    int cnt = tend - tstart;               // 86 or 87

    const float4* src = g_tri2 + ((size_t)b * NT + tstart) * F4_PER_TRI;
    for (int i = tid; i < cnt * F4_PER_TRI; i += TPB)
        sT[i] = src[i];
    __syncthreads();
#pragma unroll 2
    for (int t = 0; t < cnt; t++) {
        const ulonglong2* tp = reinterpret_cast<const ulonglong2*>(sT + t * F4_PER_TRI);
        tri_pair(tp, px2[0], py2[0], pz2[0], NEG1, dm[0], dm[1]);
        tri_pair(tp, px2[1], py2[1], pz2[1], NEG1, dm[2], dm[3]);
    }
#pragma unroll
    for (int k = 0; k < PPT; k++)
        atomicMin(&g_dmin[b * NP + ibase + k * TPB], __float_as_uint(dm[k]));
}

// Kernel 3a: parallel partial reduce. 64 blocks (16 slices x 4 batches) x 256 thr.
__global__ void reduceA_kernel(const float* __restrict__ pc) {
    __shared__ float sd[256];
    __shared__ float sc[256];
    int tid = threadIdx.x;
    int blk = blockIdx.x;
    int b = blk >> 4;
    int slice = blk & 15;
    int i = slice * 256 + tid;
    const float* p = pc + ((size_t)b * NP + i) * 3;
    float x = p[0], y = p[1], z = p[2];
    float m = (x != 0.0f || y != 0.0f || z != 0.0f) ? 1.0f : 0.0f;
    sd[tid] = __uint_as_float(g_dmin[b * NP + i]) * m;
    sc[tid] = m;
    __syncthreads();
    for (int s = 128; s > 0; s >>= 1) {
        if (tid < s) {
            sd[tid] += sd[tid + s];
            sc[tid] += sc[tid + s];
        }
        __syncthreads();
    }
    if (tid == 0) {
        g_psum[blk] = sd[0];
        g_pcnt[blk] = sc[0];
    }
}

// Kernel 3b: deterministic fixed-order final combine.
__global__ void reduceB_kernel(float* __restrict__ out) {
    if (threadIdx.x == 0) {
        float acc = 0.0f;
        for (int b = 0; b < NB; b++) {
            float s = 0.0f, c = 0.0f;
#pragma unroll
            for (int j = 0; j < 16; j++) {
                s += g_psum[b * 16 + j];
                c += g_pcnt[b * 16 + j];
            }
            acc += s / fmaxf(c, 1.0f);
        }
        out[0] = acc * (1.0f / NB);
    }
}

extern "C" void kernel_launch(void* const* d_in, const int* in_sizes, int n_in,
                              void* d_out, int out_size) {
    const float* vertices = (const float*)d_in[0];
    const float* pc = (const float*)d_in[1];
    const int* faces = (const int*)d_in[2];
    float* out = (float*)d_out;

    tri_kernel<<<(NB * NT + 255) / 256, 256>>>(vertices, faces);
    dist_kernel<<<dim3(CHUNKS_X, NP / (PPT * TPB), NB), TPB>>>(pc);
    reduceA_kernel<<<64, 256>>>(pc);
    reduceB_kernel<<<1, 32>>>(out);
}

// round 17
// speedup vs baseline: 1.0851x; 1.0064x over previous
#include <cuda_runtime.h>

#define NB 4
#define NV 4096
#define NT 8192
#define NP 4096
#define EPSF 1e-12f
#define BIGF 3.402823466e38f

#define TPB 128
#define PPT 4              // points per thread (2 packed f32x2 streams)
#define CHUNKS_X 95        // 95*8*4 = 3040 blocks = 4x760 = 5x608 (exact waves)
#define MAX_CNT 87         // ceil(8192/95)
#define F4_PER_TRI 9       // 144 bytes per triangle, constants pre-duplicated

typedef unsigned long long ull;

static __device__ float4 g_tri2[NB * NT * F4_PER_TRI];
static __device__ unsigned int g_dmin[NB * NP];

// ---------- packed f32x2 helpers (SASS FADD2/FMUL2/FFMA2) ----------
__device__ __forceinline__ ull f2x(float lo, float hi) {
    ull r; asm("mov.b64 %0, {%1, %2};" : "=l"(r) : "f"(lo), "f"(hi)); return r;
}
__device__ __forceinline__ ull f2x_add(ull a, ull b) {
    ull r; asm("add.rn.f32x2 %0, %1, %2;" : "=l"(r) : "l"(a), "l"(b)); return r;
}
__device__ __forceinline__ ull f2x_mul(ull a, ull b) {
    ull r; asm("mul.rn.f32x2 %0, %1, %2;" : "=l"(r) : "l"(a), "l"(b)); return r;
}
__device__ __forceinline__ ull f2x_fma(ull a, ull b, ull c) {
    ull r; asm("fma.rn.f32x2 %0, %1, %2, %3;" : "=l"(r) : "l"(a), "l"(b), "l"(c)); return r;
}
__device__ __forceinline__ float f2lo(ull v) { return __uint_as_float((unsigned)v); }
__device__ __forceinline__ float f2hi(ull v) { return __uint_as_float((unsigned)(v >> 32)); }

__device__ __forceinline__ float safe_inv(float x) {
    return (fabsf(x) < EPSF) ? 1.0f : (1.0f / x);
}
__device__ __forceinline__ float sigm(float v) {
    return 1.0f / (1.0f + expf(-v));
}

// Kernel 1: per-triangle precompute (sigmoid fused), dmin init, out zero.
// Pair map: c0:(-ax,-ay) c1:(-az,abx) c2:(aby,abz) c3:(acx,acy) c4:(acz,-ab2)
//           c5:(-abac,-ac2) c6:(-iab2,-iac2) c7:(-ibc2,den) c8:(-iden,0)
__global__ void tri_kernel(const float* __restrict__ vertices,
                           const int* __restrict__ faces,
                           float* __restrict__ out) {
    int idx = blockIdx.x * blockDim.x + threadIdx.x;
    if (idx == 0) out[0] = 0.0f;                   // accumulator for reduce
    if (idx < NB * NP) g_dmin[idx] = 0x7F7FFFFFu;  // +FLT_MAX bits
    if (idx >= NB * NT) return;
    int b = idx >> 13;
    int t = idx & (NT - 1);
    int i0 = faces[t * 3 + 0], i1 = faces[t * 3 + 1], i2 = faces[t * 3 + 2];
    const float* base = vertices + (size_t)b * 3 * NV;   // layout (3, NV) per batch
    float ax = sigm(base[i0]), ay = sigm(base[NV + i0]), az = sigm(base[2 * NV + i0]);
    float bx = sigm(base[i1]), by = sigm(base[NV + i1]), bz = sigm(base[2 * NV + i1]);
    float cx = sigm(base[i2]), cy = sigm(base[NV + i2]), cz = sigm(base[2 * NV + i2]);
    float abx = bx - ax, aby = by - ay, abz = bz - az;
    float acx = cx - ax, acy = cy - ay, acz = cz - az;
    float bcx = cx - bx, bcy = cy - by, bcz = cz - bz;
    float ab2  = abx * abx + aby * aby + abz * abz;
    float ac2  = acx * acx + acy * acy + acz * acz;
    float abac = abx * acx + aby * acy + abz * acz;
    float bc2  = bcx * bcx + bcy * bcy + bcz * bcz;
    float den  = ab2 * ac2 - abac * abac;   // == va+vb+vc
    float4* o = g_tri2 + (size_t)idx * F4_PER_TRI;
    o[0] = make_float4(-ax, -ax, -ay, -ay);
    o[1] = make_float4(-az, -az, abx, abx);
    o[2] = make_float4(aby, aby, abz, abz);
    o[3] = make_float4(acx, acx, acy, acy);
    o[4] = make_float4(acz, acz, -ab2, -ab2);
    o[5] = make_float4(-abac, -abac, -ac2, -ac2);
    o[6] = make_float4(-safe_inv(ab2), -safe_inv(ab2), -safe_inv(ac2), -safe_inv(ac2));
    o[7] = make_float4(-safe_inv(bc2), -safe_inv(bc2), den, den);
    o[8] = make_float4(-safe_inv(den), -safe_inv(den), 0.0f, 0.0f);
}

// Min-of-features closest distance, one triangle vs two packed points.
// m = min(pa2, pb2, pc2,
//         lineAB if 0<d1<ab2, lineAC if 0<d2<ac2 (d6<0), lineBC if e>0 && f>0,
//         face   if va,vb,vc > 0)
__device__ __forceinline__ void tri_pair(const ulonglong2* __restrict__ tp,
                                         ull px, ull py, ull pz, ull NEG1,
                                         float& m0, float& m1)
{
    ulonglong2 c0 = tp[0], c1 = tp[1], c2 = tp[2], c3 = tp[3], c4 = tp[4];
    ull apx = f2x_add(px, c0.x);
    ull apy = f2x_add(py, c0.y);
    ull apz = f2x_add(pz, c1.x);
    ull pa2 = f2x_fma(apx, apx, f2x_fma(apy, apy, f2x_mul(apz, apz)));
    ull d1  = f2x_fma(c1.y, apx, f2x_fma(c2.x, apy, f2x_mul(c2.y, apz)));
    ull d2  = f2x_fma(c3.x, apx, f2x_fma(c3.y, apy, f2x_mul(c4.x, apz)));
    ulonglong2 c5 = tp[5], c6 = tp[6], c7 = tp[7], c8 = tp[8];
    ull d3 = f2x_add(d1, c4.y);            // d1 - ab2
    ull d4 = f2x_add(d2, c5.x);            // d2 - abac
    ull d5 = f2x_add(d1, c5.x);            // d1 - abac
    ull d6 = f2x_add(d2, c5.y);            // d2 - ac2
    ull pb2 = f2x_fma(f2x_add(d1, d3), NEG1, pa2);
    ull pc2 = f2x_fma(f2x_add(d2, d6), NEG1, pa2);
    ull e = f2x_fma(d3, NEG1, d4);
    ull f = f2x_fma(d6, NEG1, d5);
    ull vAB = f2x_fma(f2x_mul(d1, d1), c6.x, pa2);
    ull vAC = f2x_fma(f2x_mul(d2, d2), c6.y, pa2);
    ull vBC = f2x_fma(f2x_mul(e, e), c7.x, pb2);
    ull vb = f2x_fma(f2x_mul(d1, d6), NEG1, f2x_mul(d5, d2));
    ull vc = f2x_fma(f2x_mul(d3, d2), NEG1, f2x_mul(d1, d4));
    ull va = f2x_fma(f2x_add(vb, vc), NEG1, c7.y);
    ull dI = f2x_fma(f2x_fma(vc, d2, f2x_mul(vb, d1)), c8.x, pa2);

    // lane 0
    {
        float m = fminf(f2lo(pa2), fminf(f2lo(pb2), f2lo(pc2)));
        if (f2lo(d1) > 0.0f && f2lo(d3) < 0.0f) m = fminf(m, f2lo(vAB));
        if (f2lo(d2) > 0.0f && f2lo(d6) < 0.0f) m = fminf(m, f2lo(vAC));
        if (f2lo(e) > 0.0f && f2lo(f) > 0.0f) m = fminf(m, f2lo(vBC));
        if (fminf(f2lo(va), fminf(f2lo(vb), f2lo(vc))) > 0.0f) m = fminf(m, f2lo(dI));
        m0 = fminf(m0, m);
    }
    // lane 1
    {
        float m = fminf(f2hi(pa2), fminf(f2hi(pb2), f2hi(pc2)));
        if (f2hi(d1) > 0.0f && f2hi(d3) < 0.0f) m = fminf(m, f2hi(vAB));
        if (f2hi(d2) > 0.0f && f2hi(d6) < 0.0f) m = fminf(m, f2hi(vAC));
        if (f2hi(e) > 0.0f && f2hi(f) > 0.0f) m = fminf(m, f2hi(vBC));
        if (fminf(f2hi(va), fminf(f2hi(vb), f2hi(vc))) > 0.0f) m = fminf(m, f2hi(dI));
        m1 = fminf(m1, m);
    }
}

// Kernel 2: brute-force min over triangles, packed f32x2, smem-staged tris.
// R14-winning config: grid 95x8x4 = 3040 blocks (86-87 tris each), smem padded
// to ~39KB to pin residency at 5 blocks/SM (760 resident on 152 SMs -> 4 exact
// waves; 4/SM fallback -> 608 -> 5 exact waves). No max-blocks clamp (R15:
// launch_bounds(,6) forces hot-loop spills, +18us).
__global__ void __launch_bounds__(TPB) dist_kernel(const float* __restrict__ pc) {
    __shared__ float4 sT[MAX_CNT * F4_PER_TRI];
    __shared__ char s_pad[26496];          // occupancy pin: total smem > 228KB/6
    int b = blockIdx.z;
    int tid = threadIdx.x;
    if (tid > 100000) ((volatile char*)s_pad)[0] = 1;   // keep pad allocated
    const float* P = pc + (size_t)b * NP * 3;
    int ibase = blockIdx.y * (PPT * TPB) + tid;

    float px[PPT], py[PPT], pz[PPT];
#pragma unroll
    for (int k = 0; k < PPT; k++) {
        int i = ibase + k * TPB;
        px[k] = P[i * 3 + 0];
        py[k] = P[i * 3 + 1];
        pz[k] = P[i * 3 + 2];
    }
    ull px2[2], py2[2], pz2[2];
#pragma unroll
    for (int j = 0; j < 2; j++) {
        px2[j] = f2x(px[2 * j], px[2 * j + 1]);
        py2[j] = f2x(py[2 * j], py[2 * j + 1]);
        pz2[j] = f2x(pz[2 * j], pz[2 * j + 1]);
    }
    const ull NEG1 = f2x(-1.0f, -1.0f);
    float dm[PPT];
#pragma unroll
    for (int k = 0; k < PPT; k++) dm[k] = BIGF;

    int x = blockIdx.x;
    int tstart = (x * NT) / CHUNKS_X;
    int tend = ((x + 1) * NT) / CHUNKS_X;
    int cnt = tend - tstart;               // 86 or 87

    const float4* src = g_tri2 + ((size_t)b * NT + tstart) * F4_PER_TRI;
    for (int i = tid; i < cnt * F4_PER_TRI; i += TPB)
        sT[i] = src[i];
    __syncthreads();
#pragma unroll 2
    for (int t = 0; t < cnt; t++) {
        const ulonglong2* tp = reinterpret_cast<const ulonglong2*>(sT + t * F4_PER_TRI);
        tri_pair(tp, px2[0], py2[0], pz2[0], NEG1, dm[0], dm[1]);
        tri_pair(tp, px2[1], py2[1], pz2[1], NEG1, dm[2], dm[3]);
    }
#pragma unroll
    for (int k = 0; k < PPT; k++)
        atomicMin(&g_dmin[b * NP + ibase + k * TPB], __float_as_uint(dm[k]));
}

// Kernel 3: single-stage reduction. One block per batch (4 blocks x 1024 thr),
// each thread 4 coalesced points, smem tree, then one float atomicAdd into out.
__global__ void reduce_kernel(const float* __restrict__ pc, float* __restrict__ out) {
    __shared__ float sd[1024];
    __shared__ float sc[1024];
    int b = blockIdx.x;
    int tid = threadIdx.x;
    float ld = 0.0f, lc = 0.0f;
#pragma unroll
    for (int k = 0; k < 4; k++) {
        int i = tid + k * 1024;
        const float* p = pc + ((size_t)b * NP + i) * 3;
        float x = p[0], y = p[1], z = p[2];
        float m = (x != 0.0f || y != 0.0f || z != 0.0f) ? 1.0f : 0.0f;
        ld += __uint_as_float(g_dmin[b * NP + i]) * m;
        lc += m;
    }
    sd[tid] = ld;
    sc[tid] = lc;
    __syncthreads();
    for (int s = 512; s > 0; s >>= 1) {
        if (tid < s) {
            sd[tid] += sd[tid + s];
            sc[tid] += sc[tid + s];
        }
        __syncthreads();
    }
    if (tid == 0)
        atomicAdd(out, 0.25f * sd[0] / fmaxf(sc[0], 1.0f));
}

extern "C" void kernel_launch(void* const* d_in, const int* in_sizes, int n_in,
                              void* d_out, int out_size) {
    const float* vertices = (const float*)d_in[0];
    const float* pc = (const float*)d_in[1];
    const int* faces = (const int*)d_in[2];
    float* out = (float*)d_out;

    tri_kernel<<<(NB * NT + 255) / 256, 256>>>(vertices, faces, out);
    dist_kernel<<<dim3(CHUNKS_X, NP / (PPT * TPB), NB), TPB>>>(pc);
    reduce_kernel<<<NB, 1024>>>(pc, out);
}